// round 2
// baseline (speedup 1.0000x reference)
#include <cuda_runtime.h>
#include <cstdint>

// Problem sizes
#define S   4096
#define II  64
#define H   1024
#define G4  4096      // 4*H
#define NCTA 128
#define UPC  8        // hidden units per CTA (1 per warp, 8 warps)

// ---------------------------------------------------------------------------
// Device-global scratch (allocation-free rule: __device__ arrays only)
// ---------------------------------------------------------------------------
__device__ float    g_xg[(size_t)S * G4];   // 64 MB: precomputed input gates
__device__ float    g_h[2][H];              // double-buffered hidden state
__device__ unsigned g_flags[NCTA];          // per-CTA step completion flags

// ---------------------------------------------------------------------------
// Helpers
// ---------------------------------------------------------------------------
__device__ __forceinline__ unsigned long long pk2(float x, float y) {
    unsigned long long r;
    asm("mov.b64 %0, {%1,%2};" : "=l"(r) : "f"(x), "f"(y));
    return r;
}
__device__ __forceinline__ void upk2(unsigned long long a, float& x, float& y) {
    asm("mov.b64 {%0,%1}, %2;" : "=f"(x), "=f"(y) : "l"(a));
}
#define FMA2(acc, a, b) \
    asm("fma.rn.f32x2 %0, %1, %2, %0;" : "+l"(acc) : "l"(a), "l"(b))

__device__ __forceinline__ float sigf(float x) {
    return 1.0f / (1.0f + __expf(-x));
}
__device__ __forceinline__ float tanhfast(float x) {
    float ax = fabsf(x);
    float e  = __expf(-2.0f * ax);          // in (0,1], overflow-free
    float t  = (1.0f - e) / (1.0f + e);
    return copysignf(t, x);
}

// ---------------------------------------------------------------------------
// Kernel 0: reset state between graph replays (determinism requirement)
// ---------------------------------------------------------------------------
__global__ void reset_kernel() {
    int i = threadIdx.x;
    if (i < H)    { g_h[0][i] = 0.0f; g_h[1][i] = 0.0f; }
    if (i < NCTA) g_flags[i] = 0u;
}

// ---------------------------------------------------------------------------
// Kernel 1: x_gates = input @ W_ih^T + (b_ih + b_hh)   -> g_xg[S][4H]
// grid (64 row-blocks, 64 t-blocks), 256 threads
// Each block: 64 rows x 64 timesteps. W row held in registers, input tile in SMEM.
// ---------------------------------------------------------------------------
__global__ void __launch_bounds__(256) xg_kernel(
    const float* __restrict__ x,
    const float* __restrict__ Wih,
    const float* __restrict__ bih,
    const float* __restrict__ bhh)
{
    __shared__ __align__(16) float xs[64 * II];   // 16 KB input tile

    const int r0 = blockIdx.x * 64;
    const int t0 = blockIdx.y * 64;

    // cooperative load of input tile (contiguous 16 KB)
    {
        const float4* src = (const float4*)(x + (size_t)t0 * II);
        float4* dst = (float4*)xs;
        #pragma unroll
        for (int i = threadIdx.x; i < 64 * II / 4; i += 256) dst[i] = src[i];
    }
    __syncthreads();

    const int rl  = threadIdx.x & 63;
    const int tg  = threadIdx.x >> 6;      // 0..3, each handles 16 timesteps
    const int row = r0 + rl;

    float w[II];
    #pragma unroll
    for (int j = 0; j < II / 4; j++) {
        float4 v = ((const float4*)(Wih + (size_t)row * II))[j];
        w[4*j+0] = v.x; w[4*j+1] = v.y; w[4*j+2] = v.z; w[4*j+3] = v.w;
    }
    const float b = bih[row] + bhh[row];

    #pragma unroll
    for (int tt = 0; tt < 16; tt++) {
        const int tl = tg * 16 + tt;
        float acc = b;
        #pragma unroll
        for (int j = 0; j < II; j++)
            acc = fmaf(w[j], xs[tl * II + j], acc);
        g_xg[(size_t)(t0 + tl) * G4 + row] = acc;
    }
}

// ---------------------------------------------------------------------------
// Kernel 2: persistent LSTM recurrence.
// 128 CTAs x 256 threads, all co-resident (1 CTA/SM by register pressure).
// Warp w of CTA b owns hidden unit u = b*8 + w (rows u, H+u, 2H+u, 3H+u of W_hh).
// Lane l owns column pairs (2l + 64k, 2l+1 + 64k), k = 0..15 -> 64 packed f32x2
// weights per thread live in registers for all 4096 steps.
// Step barrier: per-CTA release flag in GMEM + 128 acquire-pollers.
// ---------------------------------------------------------------------------
__global__ void __launch_bounds__(256, 1) rec_kernel(const float* __restrict__ Whh)
{
    __shared__ __align__(16) float hs[H];

    const int tid  = threadIdx.x;
    const int lane = tid & 31;
    const int wrp  = tid >> 5;               // 0..7
    const int cta  = blockIdx.x;
    const int u    = cta * UPC + wrp;        // hidden unit 0..1023

    // Load weight slice into registers (coalesced float2 loads)
    unsigned long long wq[4][16];
    #pragma unroll
    for (int g = 0; g < 4; g++) {
        const float2* base = (const float2*)(Whh + (size_t)(g * H + u) * H) + lane;
        #pragma unroll
        for (int k = 0; k < 16; k++) {
            float2 v = base[k * 32];
            wq[g][k] = pk2(v.x, v.y);
        }
    }

    float c = 0.0f;                          // cell state (lane 0 only)
    const unsigned full = 0xffffffffu;

    #pragma unroll 1
    for (int t = 0; t < S; t++) {
        // Prefetch this step's input-gate contributions (lane 0 of each warp)
        float xg0 = 0.f, xg1 = 0.f, xg2 = 0.f, xg3 = 0.f;
        if (lane == 0) {
            const float* xp = g_xg + (size_t)t * G4 + u;
            xg0 = __ldcg(xp);
            xg1 = __ldcg(xp + H);
            xg2 = __ldcg(xp + 2 * H);
            xg3 = __ldcg(xp + 3 * H);
        }

        // Wait for h_t to be published by every CTA (h_0 = 0, no wait)
        if (t > 0 && tid < NCTA) {
            unsigned v;
            do {
                asm volatile("ld.global.acquire.gpu.u32 %0, [%1];"
                             : "=r"(v) : "l"(g_flags + tid));
            } while (v < (unsigned)t);
        }
        __syncthreads();

        // Stage h_t into SMEM (256 x float4 = 4 KB, L2-bypass of stale L1)
        {
            const float4* hp = (const float4*)g_h[t & 1];
            ((float4*)hs)[tid] = __ldcg(hp + tid);
        }
        __syncthreads();

        // Mat-vec: 4 gates x 16 packed pairs, conflict-free LDS.64
        unsigned long long a0 = 0ull, a1 = 0ull, a2 = 0ull, a3 = 0ull;
        const unsigned long long* h2 = (const unsigned long long*)hs + lane;
        #pragma unroll
        for (int k = 0; k < 16; k++) {
            unsigned long long hv = h2[k * 32];
            FMA2(a0, wq[0][k], hv);
            FMA2(a1, wq[1][k], hv);
            FMA2(a2, wq[2][k], hv);
            FMA2(a3, wq[3][k], hv);
        }
        float s0, s1, s2, s3, xl, xh;
        upk2(a0, xl, xh); s0 = xl + xh;
        upk2(a1, xl, xh); s1 = xl + xh;
        upk2(a2, xl, xh); s2 = xl + xh;
        upk2(a3, xl, xh); s3 = xl + xh;

        #pragma unroll
        for (int off = 16; off > 0; off >>= 1) {
            s0 += __shfl_xor_sync(full, s0, off);
            s1 += __shfl_xor_sync(full, s1, off);
            s2 += __shfl_xor_sync(full, s2, off);
            s3 += __shfl_xor_sync(full, s3, off);
        }

        if (lane == 0) {
            const float gi = xg0 + s0;
            const float gf = xg1 + s1;
            const float gg = xg2 + s2;
            const float go = xg3 + s3;
            const float i_ = sigf(gi);
            const float f_ = sigf(gf);
            const float g_ = tanhfast(gg);
            const float o_ = sigf(go);
            c = fmaf(f_, c, i_ * g_);
            const float hnew = o_ * tanhfast(c);
            g_h[(t + 1) & 1][u] = hnew;
        }
        __syncthreads();          // all lane-0 stores done before flag release

        if (tid == 0) {
            __threadfence();
            asm volatile("st.global.release.gpu.u32 [%0], %1;"
                         :: "l"(g_flags + cta), "r"(t + 1));
        }
    }
}

// ---------------------------------------------------------------------------
// Kernel 3: out = h_S @ W_lin^T + b_lin   (O = 1), deterministic reduction
// h_S lives in g_h[S & 1] = g_h[0]
// ---------------------------------------------------------------------------
__global__ void __launch_bounds__(1024) out_kernel(
    const float* __restrict__ Wlin,
    const float* __restrict__ blin,
    float* __restrict__ out)
{
    __shared__ float red[32];
    const int tid = threadIdx.x;
    float v = g_h[0][tid] * Wlin[tid];
    #pragma unroll
    for (int off = 16; off > 0; off >>= 1)
        v += __shfl_xor_sync(0xffffffffu, v, off);
    if ((tid & 31) == 0) red[tid >> 5] = v;
    __syncthreads();
    if (tid < 32) {
        float x = red[tid];
        #pragma unroll
        for (int off = 16; off > 0; off >>= 1)
            x += __shfl_xor_sync(0xffffffffu, x, off);
        if (tid == 0) out[0] = x + blin[0];
    }
}

// ---------------------------------------------------------------------------
// kernel_launch (graph-capturable: plain launches only)
// Input order: input_seq, W_ih, W_hh, b_ih, b_hh, W_lin, b_lin (all fp32)
// ---------------------------------------------------------------------------
extern "C" void kernel_launch(void* const* d_in, const int* in_sizes, int n_in,
                              void* d_out, int out_size)
{
    const float* x    = (const float*)d_in[0];
    const float* Wih  = (const float*)d_in[1];
    const float* Whh  = (const float*)d_in[2];
    const float* bih  = (const float*)d_in[3];
    const float* bhh  = (const float*)d_in[4];
    const float* Wlin = (const float*)d_in[5];
    const float* blin = (const float*)d_in[6];
    float* out = (float*)d_out;

    reset_kernel<<<1, 1024>>>();

    dim3 gxg(G4 / 64, S / 64);               // (64, 64)
    xg_kernel<<<gxg, 256>>>(x, Wih, bih, bhh);

    rec_kernel<<<NCTA, 256>>>(Whh);

    out_kernel<<<1, 1024>>>(Wlin, blin, out);
}

// round 3
// speedup vs baseline: 1.1770x; 1.1770x over previous
#include <cuda_runtime.h>
#include <cstdint>

// Problem sizes
#define S   4096
#define II  64
#define H   1024
#define G4  4096      // 4*H
#define NCTA 128
#define UPC  8        // hidden units per CTA (1 per warp, 8 warps)

// ---------------------------------------------------------------------------
// Device-global scratch (allocation-free rule: __device__ arrays only)
// ---------------------------------------------------------------------------
__device__ float    g_xg[(size_t)S * G4];   // 64 MB: precomputed input gates
__device__ float    g_h[2][H];              // double-buffered hidden state
__device__ unsigned g_flags[NCTA];          // per-CTA step completion flags

// ---------------------------------------------------------------------------
// Helpers
// ---------------------------------------------------------------------------
__device__ __forceinline__ unsigned long long pk2(float x, float y) {
    unsigned long long r;
    asm("mov.b64 %0, {%1,%2};" : "=l"(r) : "f"(x), "f"(y));
    return r;
}
__device__ __forceinline__ void upk2(unsigned long long a, float& x, float& y) {
    asm("mov.b64 {%0,%1}, %2;" : "=f"(x), "=f"(y) : "l"(a));
}
#define FMA2(acc, a, b) \
    asm("fma.rn.f32x2 %0, %1, %2, %0;" : "+l"(acc) : "l"(a), "l"(b))

__device__ __forceinline__ float sigf(float x) {
    return 1.0f / (1.0f + __expf(-x));
}
__device__ __forceinline__ float tanhfast(float x) {
    float ax = fabsf(x);
    float e  = __expf(-2.0f * ax);          // in (0,1], overflow-free
    float t  = (1.0f - e) / (1.0f + e);
    return copysignf(t, x);
}

// ---------------------------------------------------------------------------
// Kernel 0: reset state between graph replays (determinism requirement)
// ---------------------------------------------------------------------------
__global__ void reset_kernel() {
    int i = threadIdx.x;
    if (i < H)    { g_h[0][i] = 0.0f; g_h[1][i] = 0.0f; }
    if (i < NCTA) g_flags[i] = 0u;
}

// ---------------------------------------------------------------------------
// Kernel 1: x_gates = input @ W_ih^T + (b_ih + b_hh)   -> g_xg[S][4H]
// grid (64 row-blocks, 64 t-blocks), 256 threads
// Each block: 64 rows x 64 timesteps. W row held in registers, input tile in SMEM.
// ---------------------------------------------------------------------------
__global__ void __launch_bounds__(256) xg_kernel(
    const float* __restrict__ x,
    const float* __restrict__ Wih,
    const float* __restrict__ bih,
    const float* __restrict__ bhh)
{
    __shared__ __align__(16) float xs[64 * II];   // 16 KB input tile

    const int r0 = blockIdx.x * 64;
    const int t0 = blockIdx.y * 64;

    // cooperative load of input tile (contiguous 16 KB)
    {
        const float4* src = (const float4*)(x + (size_t)t0 * II);
        float4* dst = (float4*)xs;
        #pragma unroll
        for (int i = threadIdx.x; i < 64 * II / 4; i += 256) dst[i] = src[i];
    }
    __syncthreads();

    const int rl  = threadIdx.x & 63;
    const int tg  = threadIdx.x >> 6;      // 0..3, each handles 16 timesteps
    const int row = r0 + rl;

    float w[II];
    #pragma unroll
    for (int j = 0; j < II / 4; j++) {
        float4 v = ((const float4*)(Wih + (size_t)row * II))[j];
        w[4*j+0] = v.x; w[4*j+1] = v.y; w[4*j+2] = v.z; w[4*j+3] = v.w;
    }
    const float b = bih[row] + bhh[row];

    #pragma unroll
    for (int tt = 0; tt < 16; tt++) {
        const int tl = tg * 16 + tt;
        float acc = b;
        #pragma unroll
        for (int j = 0; j < II; j++)
            acc = fmaf(w[j], xs[tl * II + j], acc);
        g_xg[(size_t)(t0 + tl) * G4 + row] = acc;
    }
}

// ---------------------------------------------------------------------------
// Kernel 2: persistent LSTM recurrence.
// 128 CTAs x 256 threads, all co-resident (1 CTA/SM by register pressure).
// Warp w of CTA b owns hidden unit u = b*8 + w (rows u, H+u, 2H+u, 3H+u of W_hh).
// Lane l owns column pairs (2l + 64k, 2l+1 + 64k), k = 0..15 -> 64 packed f32x2
// weights per thread live in registers for all 4096 steps.
// Step barrier: per-CTA release flag in GMEM + 128 acquire-pollers.
// ---------------------------------------------------------------------------
__global__ void __launch_bounds__(256, 1) rec_kernel(const float* __restrict__ Whh)
{
    __shared__ __align__(16) float hs[H];

    const int tid  = threadIdx.x;
    const int lane = tid & 31;
    const int wrp  = tid >> 5;               // 0..7
    const int cta  = blockIdx.x;
    const int u    = cta * UPC + wrp;        // hidden unit 0..1023

    // Load weight slice into registers (coalesced float2 loads)
    unsigned long long wq[4][16];
    #pragma unroll
    for (int g = 0; g < 4; g++) {
        const float2* base = (const float2*)(Whh + (size_t)(g * H + u) * H) + lane;
        #pragma unroll
        for (int k = 0; k < 16; k++) {
            float2 v = base[k * 32];
            wq[g][k] = pk2(v.x, v.y);
        }
    }

    float c = 0.0f;                          // cell state (lane 0 only)
    const unsigned full = 0xffffffffu;

    #pragma unroll 1
    for (int t = 0; t < S; t++) {
        // Prefetch this step's input-gate contributions (lane 0 of each warp)
        float xg0 = 0.f, xg1 = 0.f, xg2 = 0.f, xg3 = 0.f;
        if (lane == 0) {
            const float* xp = g_xg + (size_t)t * G4 + u;
            xg0 = __ldcg(xp);
            xg1 = __ldcg(xp + H);
            xg2 = __ldcg(xp + 2 * H);
            xg3 = __ldcg(xp + 3 * H);
        }

        // Wait for h_t to be published by every CTA (h_0 = 0, no wait)
        if (t > 0 && tid < NCTA) {
            unsigned v;
            do {
                asm volatile("ld.global.acquire.gpu.u32 %0, [%1];"
                             : "=r"(v) : "l"(g_flags + tid));
            } while (v < (unsigned)t);
        }
        __syncthreads();

        // Stage h_t into SMEM (256 x float4 = 4 KB, L2-bypass of stale L1)
        {
            const float4* hp = (const float4*)g_h[t & 1];
            ((float4*)hs)[tid] = __ldcg(hp + tid);
        }
        __syncthreads();

        // Mat-vec: 4 gates x 16 packed pairs, conflict-free LDS.64
        unsigned long long a0 = 0ull, a1 = 0ull, a2 = 0ull, a3 = 0ull;
        const unsigned long long* h2 = (const unsigned long long*)hs + lane;
        #pragma unroll
        for (int k = 0; k < 16; k++) {
            unsigned long long hv = h2[k * 32];
            FMA2(a0, wq[0][k], hv);
            FMA2(a1, wq[1][k], hv);
            FMA2(a2, wq[2][k], hv);
            FMA2(a3, wq[3][k], hv);
        }
        float s0, s1, s2, s3, xl, xh;
        upk2(a0, xl, xh); s0 = xl + xh;
        upk2(a1, xl, xh); s1 = xl + xh;
        upk2(a2, xl, xh); s2 = xl + xh;
        upk2(a3, xl, xh); s3 = xl + xh;

        #pragma unroll
        for (int off = 16; off > 0; off >>= 1) {
            s0 += __shfl_xor_sync(full, s0, off);
            s1 += __shfl_xor_sync(full, s1, off);
            s2 += __shfl_xor_sync(full, s2, off);
            s3 += __shfl_xor_sync(full, s3, off);
        }

        if (lane == 0) {
            const float gi = xg0 + s0;
            const float gf = xg1 + s1;
            const float gg = xg2 + s2;
            const float go = xg3 + s3;
            const float i_ = sigf(gi);
            const float f_ = sigf(gf);
            const float g_ = tanhfast(gg);
            const float o_ = sigf(go);
            c = fmaf(f_, c, i_ * g_);
            const float hnew = o_ * tanhfast(c);
            g_h[(t + 1) & 1][u] = hnew;
        }
        __syncthreads();          // all lane-0 stores done before flag release

        if (tid == 0) {
            __threadfence();
            asm volatile("st.global.release.gpu.u32 [%0], %1;"
                         :: "l"(g_flags + cta), "r"(t + 1));
        }
    }
}

// ---------------------------------------------------------------------------
// Kernel 3: out = h_S @ W_lin^T + b_lin   (O = 1), deterministic reduction
// h_S lives in g_h[S & 1] = g_h[0]
// ---------------------------------------------------------------------------
__global__ void __launch_bounds__(1024) out_kernel(
    const float* __restrict__ Wlin,
    const float* __restrict__ blin,
    float* __restrict__ out)
{
    __shared__ float red[32];
    const int tid = threadIdx.x;
    float v = g_h[0][tid] * Wlin[tid];
    #pragma unroll
    for (int off = 16; off > 0; off >>= 1)
        v += __shfl_xor_sync(0xffffffffu, v, off);
    if ((tid & 31) == 0) red[tid >> 5] = v;
    __syncthreads();
    if (tid < 32) {
        float x = red[tid];
        #pragma unroll
        for (int off = 16; off > 0; off >>= 1)
            x += __shfl_xor_sync(0xffffffffu, x, off);
        if (tid == 0) out[0] = x + blin[0];
    }
}

// ---------------------------------------------------------------------------
// kernel_launch (graph-capturable: plain launches only)
// Input order: input_seq, W_ih, W_hh, b_ih, b_hh, W_lin, b_lin (all fp32)
// ---------------------------------------------------------------------------
extern "C" void kernel_launch(void* const* d_in, const int* in_sizes, int n_in,
                              void* d_out, int out_size)
{
    const float* x    = (const float*)d_in[0];
    const float* Wih  = (const float*)d_in[1];
    const float* Whh  = (const float*)d_in[2];
    const float* bih  = (const float*)d_in[3];
    const float* bhh  = (const float*)d_in[4];
    const float* Wlin = (const float*)d_in[5];
    const float* blin = (const float*)d_in[6];
    float* out = (float*)d_out;

    reset_kernel<<<1, 1024>>>();

    dim3 gxg(G4 / 64, S / 64);               // (64, 64)
    xg_kernel<<<gxg, 256>>>(x, Wih, bih, bhh);

    rec_kernel<<<NCTA, 256>>>(Whh);

    out_kernel<<<1, 1024>>>(Wlin, blin, out);
}

// round 4
// speedup vs baseline: 4.0384x; 3.4309x over previous
#include <cuda_runtime.h>
#include <cstdint>

// Problem sizes
#define S   4096
#define II  64
#define H   1024
#define G4  4096      // 4*H
#define NCTA 128
#define UPC  8        // hidden units per CTA (1 per warp, 8 warps)

// ---------------------------------------------------------------------------
// Device-global scratch (allocation-free rule: __device__ arrays only)
// ---------------------------------------------------------------------------
__device__ float    g_xg[(size_t)S * G4];   // 64 MB: precomputed input gates
__device__ float    g_h[2][H];              // double-buffered hidden state
__device__ unsigned g_cnt;                  // single monotonic step counter

// ---------------------------------------------------------------------------
// Helpers
// ---------------------------------------------------------------------------
__device__ __forceinline__ unsigned long long pk2(float x, float y) {
    unsigned long long r;
    asm("mov.b64 %0, {%1,%2};" : "=l"(r) : "f"(x), "f"(y));
    return r;
}
__device__ __forceinline__ void upk2(unsigned long long a, float& x, float& y) {
    asm("mov.b64 {%0,%1}, %2;" : "=f"(x), "=f"(y) : "l"(a));
}
#define FMA2(acc, a, b) \
    asm("fma.rn.f32x2 %0, %1, %2, %0;" : "+l"(acc) : "l"(a), "l"(b))

__device__ __forceinline__ float sigf(float x) {
    return 1.0f / (1.0f + __expf(-x));
}
__device__ __forceinline__ float tanhfast(float x) {
    float ax = fabsf(x);
    float e  = __expf(-2.0f * ax);          // in (0,1], overflow-free
    float t  = __fdividef(1.0f - e, 1.0f + e);
    return copysignf(t, x);
}

// ---------------------------------------------------------------------------
// Kernel 0: reset state between graph replays (determinism requirement)
// ---------------------------------------------------------------------------
__global__ void reset_kernel() {
    int i = threadIdx.x;
    if (i < H)    { g_h[0][i] = 0.0f; g_h[1][i] = 0.0f; }
    if (i == 0)   g_cnt = 0u;
}

// ---------------------------------------------------------------------------
// Kernel 1: x_gates = input @ W_ih^T + (b_ih + b_hh)   -> g_xg[S][4H]
// ---------------------------------------------------------------------------
__global__ void __launch_bounds__(256) xg_kernel(
    const float* __restrict__ x,
    const float* __restrict__ Wih,
    const float* __restrict__ bih,
    const float* __restrict__ bhh)
{
    __shared__ __align__(16) float xs[64 * II];   // 16 KB input tile

    const int r0 = blockIdx.x * 64;
    const int t0 = blockIdx.y * 64;

    {
        const float4* src = (const float4*)(x + (size_t)t0 * II);
        float4* dst = (float4*)xs;
        #pragma unroll
        for (int i = threadIdx.x; i < 64 * II / 4; i += 256) dst[i] = src[i];
    }
    __syncthreads();

    const int rl  = threadIdx.x & 63;
    const int tg  = threadIdx.x >> 6;      // 0..3, each handles 16 timesteps
    const int row = r0 + rl;

    float w[II];
    #pragma unroll
    for (int j = 0; j < II / 4; j++) {
        float4 v = ((const float4*)(Wih + (size_t)row * II))[j];
        w[4*j+0] = v.x; w[4*j+1] = v.y; w[4*j+2] = v.z; w[4*j+3] = v.w;
    }
    const float b = bih[row] + bhh[row];

    #pragma unroll
    for (int tt = 0; tt < 16; tt++) {
        const int tl = tg * 16 + tt;
        float acc = b;
        #pragma unroll
        for (int j = 0; j < II; j++)
            acc = fmaf(w[j], xs[tl * II + j], acc);
        g_xg[(size_t)(t0 + tl) * G4 + row] = acc;
    }
}

// ---------------------------------------------------------------------------
// Kernel 2: persistent LSTM recurrence.
// 128 CTAs x 256 threads, 1 CTA/SM. Warp w of CTA b owns hidden unit
// u = b*8 + w. W_hh slice lives in registers (64 packed f32x2 / thread).
//
// Step barrier: single monotonic counter. Each CTA does ONE
// red.add.release.gpu per step; ONE thread per CTA polls with acquire
// loads until cnt >= 128*t. Dense W_hh bounds cross-CTA step spread to <=1,
// so the sum test is exact (a lagging CTA caps cnt at 128t-1).
// This replaces 16K pollers hammering 4 L2 lines (the R3 bottleneck).
// ---------------------------------------------------------------------------
__global__ void __launch_bounds__(256, 1) rec_kernel(const float* __restrict__ Whh)
{
    __shared__ __align__(16) float hs[H];

    const int tid  = threadIdx.x;
    const int lane = tid & 31;
    const int wrp  = tid >> 5;               // 0..7
    const int cta  = blockIdx.x;
    const int u    = cta * UPC + wrp;        // hidden unit 0..1023

    // Load weight slice into registers (coalesced float2 loads)
    unsigned long long wq[4][16];
    #pragma unroll
    for (int g = 0; g < 4; g++) {
        const float2* base = (const float2*)(Whh + (size_t)(g * H + u) * H) + lane;
        #pragma unroll
        for (int k = 0; k < 16; k++) {
            float2 v = base[k * 32];
            wq[g][k] = pk2(v.x, v.y);
        }
    }

    float c = 0.0f;                          // cell state (lane 0 only)
    const unsigned full = 0xffffffffu;

    #pragma unroll 1
    for (int t = 0; t < S; t++) {
        // Prefetch this step's input-gate contributions (lane 0 of each warp)
        float xg0 = 0.f, xg1 = 0.f, xg2 = 0.f, xg3 = 0.f;
        if (lane == 0) {
            const float* xp = g_xg + (size_t)t * G4 + u;
            xg0 = __ldcg(xp);
            xg1 = __ldcg(xp + H);
            xg2 = __ldcg(xp + 2 * H);
            xg3 = __ldcg(xp + 3 * H);
        }

        // Wait for h_t: single poller per CTA on the single counter
        if (t > 0 && tid == 0) {
            const unsigned need = (unsigned)t * NCTA;
            unsigned v;
            do {
                asm volatile("ld.global.acquire.gpu.u32 %0, [%1];"
                             : "=r"(v) : "l"(&g_cnt));
            } while (v < need);
        }
        __syncthreads();

        // Stage h_t into SMEM (256 x float4 = 4 KB, L2 reads)
        {
            const float4* hp = (const float4*)g_h[t & 1];
            ((float4*)hs)[tid] = __ldcg(hp + tid);
        }
        __syncthreads();

        // Mat-vec: 4 gates x 16 packed pairs, conflict-free LDS.64
        unsigned long long a0 = 0ull, a1 = 0ull, a2 = 0ull, a3 = 0ull;
        const unsigned long long* h2 = (const unsigned long long*)hs + lane;
        #pragma unroll
        for (int k = 0; k < 16; k++) {
            unsigned long long hv = h2[k * 32];
            FMA2(a0, wq[0][k], hv);
            FMA2(a1, wq[1][k], hv);
            FMA2(a2, wq[2][k], hv);
            FMA2(a3, wq[3][k], hv);
        }
        float s0, s1, s2, s3, xl, xh;
        upk2(a0, xl, xh); s0 = xl + xh;
        upk2(a1, xl, xh); s1 = xl + xh;
        upk2(a2, xl, xh); s2 = xl + xh;
        upk2(a3, xl, xh); s3 = xl + xh;

        #pragma unroll
        for (int off = 16; off > 0; off >>= 1) {
            s0 += __shfl_xor_sync(full, s0, off);
            s1 += __shfl_xor_sync(full, s1, off);
            s2 += __shfl_xor_sync(full, s2, off);
            s3 += __shfl_xor_sync(full, s3, off);
        }

        if (lane == 0) {
            const float gi = xg0 + s0;
            const float gf = xg1 + s1;
            const float gg = xg2 + s2;
            const float go = xg3 + s3;
            const float i_ = sigf(gi);
            const float f_ = sigf(gf);
            const float g_ = tanhfast(gg);
            const float o_ = sigf(go);
            c = fmaf(f_, c, i_ * g_);
            const float hnew = o_ * tanhfast(c);
            __stcg(&g_h[(t + 1) & 1][u], hnew);
        }
        __syncthreads();          // all lane-0 stores done before counter bump

        if (tid == 0) {
            // release-ordered add: publishes this CTA's h writes + step done
            asm volatile("red.add.release.gpu.global.u32 [%0], %1;"
                         :: "l"(&g_cnt), "r"(1u));
        }
    }
}

// ---------------------------------------------------------------------------
// Kernel 3: out = h_S @ W_lin^T + b_lin   (O = 1)
// h_S lives in g_h[S & 1] = g_h[0]
// ---------------------------------------------------------------------------
__global__ void __launch_bounds__(1024) out_kernel(
    const float* __restrict__ Wlin,
    const float* __restrict__ blin,
    float* __restrict__ out)
{
    __shared__ float red[32];
    const int tid = threadIdx.x;
    float v = g_h[0][tid] * Wlin[tid];
    #pragma unroll
    for (int off = 16; off > 0; off >>= 1)
        v += __shfl_xor_sync(0xffffffffu, v, off);
    if ((tid & 31) == 0) red[tid >> 5] = v;
    __syncthreads();
    if (tid < 32) {
        float x = red[tid];
        #pragma unroll
        for (int off = 16; off > 0; off >>= 1)
            x += __shfl_xor_sync(0xffffffffu, x, off);
        if (tid == 0) out[0] = x + blin[0];
    }
}

// ---------------------------------------------------------------------------
// kernel_launch (graph-capturable: plain launches only)
// Input order: input_seq, W_ih, W_hh, b_ih, b_hh, W_lin, b_lin (all fp32)
// ---------------------------------------------------------------------------
extern "C" void kernel_launch(void* const* d_in, const int* in_sizes, int n_in,
                              void* d_out, int out_size)
{
    const float* x    = (const float*)d_in[0];
    const float* Wih  = (const float*)d_in[1];
    const float* Whh  = (const float*)d_in[2];
    const float* bih  = (const float*)d_in[3];
    const float* bhh  = (const float*)d_in[4];
    const float* Wlin = (const float*)d_in[5];
    const float* blin = (const float*)d_in[6];
    float* out = (float*)d_out;

    reset_kernel<<<1, 1024>>>();

    dim3 gxg(G4 / 64, S / 64);               // (64, 64)
    xg_kernel<<<gxg, 256>>>(x, Wih, bih, bhh);

    rec_kernel<<<NCTA, 256>>>(Whh);

    out_kernel<<<1, 1024>>>(Wlin, blin, out);
}